// round 1
// baseline (speedup 1.0000x reference)
#include <cuda_runtime.h>
#include <math.h>

// ---------------------------------------------------------------------------
// BEiT encoder: B=64, S=197 (14x14 patches + cls), DM=768, H=12, D=64, DF=3072, L=3
// M = B*S = 12608 = 197 * 64 (divides 64-tiles exactly)
// ---------------------------------------------------------------------------

#define MROWS 12608
#define DM    768
#define DF    3072
#define SEQ   197
#define NB    64
#define NH    12
#define HD    64
#define NDREL 732

// Scratch (no cudaMalloc allowed)
__device__ float g_h  [MROWS * DM];
__device__ float g_hn [MROWS * DM];
__device__ float g_q  [MROWS * DM];
__device__ float g_k  [MROWS * DM];
__device__ float g_v  [MROWS * DM];
__device__ float g_ctx[MROWS * DM];
__device__ float g_f  [MROWS * DF];

// ---------------------------------------------------------------------------
// Patch embed: h[b,0,:] = cls; h[b,1+p,:] = x[b, p/14, p%14, :] (NHWC flatten)
// ---------------------------------------------------------------------------
__global__ void embed_kernel(const float* __restrict__ x, const float* __restrict__ cls,
                             float* __restrict__ h)
{
    int i = blockIdx.x * 256 + threadIdx.x;
    if (i >= MROWS * DM) return;
    int c = i % DM;
    int s = (i / DM) % SEQ;
    int b = i / (DM * SEQ);
    h[i] = (s == 0) ? cls[c] : x[((size_t)(b * 196 + s - 1)) * DM + c];
}

// ---------------------------------------------------------------------------
// LayerNorm over last dim (768), one block per row, 256 threads, two-pass
// ---------------------------------------------------------------------------
__global__ void ln_kernel(const float* __restrict__ x, const float* __restrict__ g,
                          const float* __restrict__ bta, float* __restrict__ y)
{
    int row = blockIdx.x;
    const float* xr = x + (size_t)row * DM;
    int t = threadIdx.x;
    float v0 = xr[t], v1 = xr[t + 256], v2 = xr[t + 512];
    __shared__ float sh[8];

    float s = v0 + v1 + v2;
    #pragma unroll
    for (int o = 16; o; o >>= 1) s += __shfl_xor_sync(0xffffffffu, s, o);
    if ((t & 31) == 0) sh[t >> 5] = s;
    __syncthreads();
    if (t == 0) { float tot = 0.f; for (int i = 0; i < 8; i++) tot += sh[i]; sh[0] = tot; }
    __syncthreads();
    float mean = sh[0] * (1.0f / 768.0f);
    __syncthreads();

    float d0 = v0 - mean, d1 = v1 - mean, d2 = v2 - mean;
    s = d0 * d0 + d1 * d1 + d2 * d2;
    #pragma unroll
    for (int o = 16; o; o >>= 1) s += __shfl_xor_sync(0xffffffffu, s, o);
    if ((t & 31) == 0) sh[t >> 5] = s;
    __syncthreads();
    if (t == 0) { float tot = 0.f; for (int i = 0; i < 8; i++) tot += sh[i]; sh[0] = tot; }
    __syncthreads();
    float rstd = rsqrtf(sh[0] * (1.0f / 768.0f) + 1e-12f);

    float* yr = y + (size_t)row * DM;
    yr[t]       = d0 * rstd * g[t]       + bta[t];
    yr[t + 256] = d1 * rstd * g[t + 256] + bta[t + 256];
    yr[t + 512] = d2 * rstd * g[t + 512] + bta[t + 512];
}

// ---------------------------------------------------------------------------
// SGEMM: C[M,N] = epilogue(A[M,K] @ W[K,N] + bias)
//   mode 0: + bias (bias may be null)
//   mode 1: gelu_exact(+ bias)
//   mode 2: res + (val + bias) * lam
// 64x64 tile, BK=16, 256 threads, 4x4 per thread. M,N multiples of 64, K of 16.
// ---------------------------------------------------------------------------
__global__ void gemm64(const float* __restrict__ A, const float* __restrict__ W,
                       const float* __restrict__ bias,
                       const float* __restrict__ res, const float* __restrict__ lam,
                       float* __restrict__ C, int M, int N, int K, int mode)
{
    __shared__ float As[16 * 65];   // [k][m], padded
    __shared__ float Ws[16 * 64];   // [k][n]
    int t  = threadIdx.x;
    int bm = blockIdx.y * 64, bn = blockIdx.x * 64;
    int tx = t & 15, ty = t >> 4;
    int arow = t >> 2, acol = (t & 3) << 2;       // A: 64 rows x 16 k
    int wrow = t >> 4, wcol = (t & 15) << 2;      // W: 16 k x 64 n

    float acc[4][4] = {};

    for (int k0 = 0; k0 < K; k0 += 16) {
        float4 a = *(const float4*)(A + (size_t)(bm + arow) * K + k0 + acol);
        As[(acol + 0) * 65 + arow] = a.x;
        As[(acol + 1) * 65 + arow] = a.y;
        As[(acol + 2) * 65 + arow] = a.z;
        As[(acol + 3) * 65 + arow] = a.w;
        *(float4*)(Ws + wrow * 64 + wcol) =
            *(const float4*)(W + (size_t)(k0 + wrow) * N + bn + wcol);
        __syncthreads();

        #pragma unroll
        for (int k = 0; k < 16; k++) {
            float a0 = As[k * 65 + ty * 4 + 0];
            float a1 = As[k * 65 + ty * 4 + 1];
            float a2 = As[k * 65 + ty * 4 + 2];
            float a3 = As[k * 65 + ty * 4 + 3];
            float4 b = *(const float4*)(Ws + k * 64 + tx * 4);
            acc[0][0] += a0 * b.x; acc[0][1] += a0 * b.y; acc[0][2] += a0 * b.z; acc[0][3] += a0 * b.w;
            acc[1][0] += a1 * b.x; acc[1][1] += a1 * b.y; acc[1][2] += a1 * b.z; acc[1][3] += a1 * b.w;
            acc[2][0] += a2 * b.x; acc[2][1] += a2 * b.y; acc[2][2] += a2 * b.z; acc[2][3] += a2 * b.w;
            acc[3][0] += a3 * b.x; acc[3][1] += a3 * b.y; acc[3][2] += a3 * b.z; acc[3][3] += a3 * b.w;
        }
        __syncthreads();
    }

    int col = bn + tx * 4;
    float bx = 0.f, by = 0.f, bz = 0.f, bw = 0.f;
    if (bias) { bx = bias[col]; by = bias[col + 1]; bz = bias[col + 2]; bw = bias[col + 3]; }
    float lx = 0.f, ly = 0.f, lz = 0.f, lw = 0.f;
    if (mode == 2) { lx = lam[col]; ly = lam[col + 1]; lz = lam[col + 2]; lw = lam[col + 3]; }

    #pragma unroll
    for (int i = 0; i < 4; i++) {
        int row = bm + ty * 4 + i;
        float4 v;
        v.x = acc[i][0] + bx; v.y = acc[i][1] + by;
        v.z = acc[i][2] + bz; v.w = acc[i][3] + bw;
        if (mode == 1) {
            v.x = 0.5f * v.x * (1.0f + erff(v.x * 0.70710678118654752f));
            v.y = 0.5f * v.y * (1.0f + erff(v.y * 0.70710678118654752f));
            v.z = 0.5f * v.z * (1.0f + erff(v.z * 0.70710678118654752f));
            v.w = 0.5f * v.w * (1.0f + erff(v.w * 0.70710678118654752f));
        } else if (mode == 2) {
            const float4 r = *(const float4*)(res + (size_t)row * N + col);
            v.x = r.x + v.x * lx; v.y = r.y + v.y * ly;
            v.z = r.z + v.z * lz; v.w = r.w + v.w * lw;
        }
        *(float4*)(C + (size_t)row * N + col) = v;
    }
}

// ---------------------------------------------------------------------------
// Attention: one block per (h, b). K,V staged in smem; warp-per-query softmax.
// Relative position index computed analytically (matches REL_IDX).
// ---------------------------------------------------------------------------
__device__ __forceinline__ int relidx(int q, int k)
{
    if (q == 0 && k == 0) return NDREL - 1;  // 731
    if (q == 0)           return NDREL - 3;  // 729
    if (k == 0)           return NDREL - 2;  // 730
    int p = q - 1, r = k - 1;
    int di = p / 14 - r / 14 + 13;
    int dj = p % 14 - r % 14 + 13;
    return di * 27 + dj;
}

#define KS_PITCH 65
#define ATT_SMEM_FLOATS (2 * SEQ * KS_PITCH + 8 * 64 + 8 * 200)
#define ATT_SMEM_BYTES  (ATT_SMEM_FLOATS * 4)

__global__ void attn_kernel(const float* __restrict__ Q, const float* __restrict__ Kg,
                            const float* __restrict__ Vg, const float* __restrict__ rel,
                            float* __restrict__ ctx)
{
    int h = blockIdx.x, b = blockIdx.y;
    extern __shared__ float sm[];
    float* Ks = sm;                          // [197][65]
    float* Vs = sm + SEQ * KS_PITCH;         // [197][65]
    float* qs = sm + 2 * SEQ * KS_PITCH;     // [8][64]
    float* Ps = qs + 8 * 64;                 // [8][200]

    int t = threadIdx.x;
    for (int idx = t; idx < SEQ * HD; idx += 256) {
        int kk = idx >> 6, d = idx & 63;
        size_t g = (size_t)(b * SEQ + kk) * DM + h * HD + d;
        Ks[kk * KS_PITCH + d] = Kg[g];
        Vs[kk * KS_PITCH + d] = Vg[g];
    }
    __syncthreads();

    int w = t >> 5, lane = t & 31;
    for (int q = w; q < SEQ; q += 8) {
        size_t qbase = (size_t)(b * SEQ + q) * DM + h * HD;
        qs[w * 64 + lane]      = Q[qbase + lane];
        qs[w * 64 + lane + 32] = Q[qbase + lane + 32];
        __syncwarp();

        float s[7];
        float mx = -1e30f;
        #pragma unroll
        for (int j = 0; j < 7; j++) {
            int kk = lane + j * 32;
            float acc = -1e30f;
            if (kk < SEQ) {
                float v = 0.f;
                #pragma unroll
                for (int d = 0; d < HD; d++) v += qs[w * 64 + d] * Ks[kk * KS_PITCH + d];
                acc = v * 0.125f + rel[relidx(q, kk) * NH + h];
            }
            s[j] = acc;
            mx = fmaxf(mx, acc);
        }
        #pragma unroll
        for (int o = 16; o; o >>= 1) mx = fmaxf(mx, __shfl_xor_sync(0xffffffffu, mx, o));

        float sum = 0.f;
        #pragma unroll
        for (int j = 0; j < 7; j++) {
            int kk = lane + j * 32;
            float e = (kk < SEQ) ? expf(s[j] - mx) : 0.f;
            s[j] = e;
            sum += e;
        }
        #pragma unroll
        for (int o = 16; o; o >>= 1) sum += __shfl_xor_sync(0xffffffffu, sum, o);
        float inv = 1.0f / sum;

        #pragma unroll
        for (int j = 0; j < 7; j++) {
            int kk = lane + j * 32;
            if (kk < SEQ) Ps[w * 200 + kk] = s[j] * inv;
        }
        __syncwarp();

        float a0 = 0.f, a1 = 0.f;
        for (int kk = 0; kk < SEQ; kk++) {
            float p = Ps[w * 200 + kk];
            a0 += p * Vs[kk * KS_PITCH + lane];
            a1 += p * Vs[kk * KS_PITCH + lane + 32];
        }
        ctx[qbase + lane]      = a0;
        ctx[qbase + lane + 32] = a1;
        __syncwarp();
    }
}

// ---------------------------------------------------------------------------
// Orchestration
// ---------------------------------------------------------------------------
extern "C" void kernel_launch(void* const* d_in, const int* in_sizes, int n_in,
                              void* d_out, int out_size)
{
    const float* x    = (const float*)d_in[0];
    const float* cls  = (const float*)d_in[1];
    const float* g1   = (const float*)d_in[2];
    const float* b1   = (const float*)d_in[3];
    const float* Wq   = (const float*)d_in[4];
    const float* bq   = (const float*)d_in[5];
    const float* Wk   = (const float*)d_in[6];
    const float* Wv   = (const float*)d_in[7];
    const float* bv   = (const float*)d_in[8];
    const float* rel  = (const float*)d_in[9];
    const float* Wo   = (const float*)d_in[10];
    const float* bo   = (const float*)d_in[11];
    const float* lam1 = (const float*)d_in[12];
    const float* g2   = (const float*)d_in[13];
    const float* b2   = (const float*)d_in[14];
    const float* Wi   = (const float*)d_in[15];
    const float* bi   = (const float*)d_in[16];
    const float* Wmo  = (const float*)d_in[17];
    const float* bmo  = (const float*)d_in[18];
    const float* lam2 = (const float*)d_in[19];

    float *h, *hn, *q, *k, *v, *ctx, *f;
    cudaGetSymbolAddress((void**)&h,   g_h);
    cudaGetSymbolAddress((void**)&hn,  g_hn);
    cudaGetSymbolAddress((void**)&q,   g_q);
    cudaGetSymbolAddress((void**)&k,   g_k);
    cudaGetSymbolAddress((void**)&v,   g_v);
    cudaGetSymbolAddress((void**)&ctx, g_ctx);
    cudaGetSymbolAddress((void**)&f,   g_f);

    cudaFuncSetAttribute(attn_kernel, cudaFuncAttributeMaxDynamicSharedMemorySize,
                         ATT_SMEM_BYTES);

    embed_kernel<<<(MROWS * DM + 255) / 256, 256>>>(x, cls, h);

    dim3 g768(DM / 64, MROWS / 64);    // (12, 197)
    dim3 g3072(DF / 64, MROWS / 64);   // (48, 197)

    for (int i = 0; i < 3; i++) {
        size_t wo  = (size_t)i * DM * DM;
        size_t wio = (size_t)i * DM * DF;

        ln_kernel<<<MROWS, 256>>>(h, g1 + i * DM, b1 + i * DM, hn);

        gemm64<<<g768, 256>>>(hn, Wq + wo, bq + i * DM, nullptr, nullptr, q,
                              MROWS, DM, DM, 0);
        gemm64<<<g768, 256>>>(hn, Wk + wo, nullptr, nullptr, nullptr, k,
                              MROWS, DM, DM, 0);
        gemm64<<<g768, 256>>>(hn, Wv + wo, bv + i * DM, nullptr, nullptr, v,
                              MROWS, DM, DM, 0);

        attn_kernel<<<dim3(NH, NB), 256, ATT_SMEM_BYTES>>>(
            q, k, v, rel + (size_t)i * NDREL * NH, ctx);

        gemm64<<<g768, 256>>>(ctx, Wo + wo, bo + i * DM, h, lam1 + i * DM, h,
                              MROWS, DM, DM, 2);

        ln_kernel<<<MROWS, 256>>>(h, g2 + i * DM, b2 + i * DM, hn);

        gemm64<<<g3072, 256>>>(hn, Wi + wio, bi + i * DF, nullptr, nullptr, f,
                               MROWS, DF, DM, 1);

        gemm64<<<g768, 256>>>(f, Wmo + wio, bmo + i * DM, h, lam2 + i * DM,
                              (i == 2) ? (float*)d_out : h,
                              MROWS, DM, DF, 2);
    }
}

// round 4
// speedup vs baseline: 1.9832x; 1.9832x over previous
#include <cuda_runtime.h>
#include <cuda_bf16.h>
#include <math.h>
#include <stdint.h>

// ---------------------------------------------------------------------------
// BEiT encoder: B=64, S=197, DM=768, H=12, D=64, DF=3072, L=3
// GEMMs via mma.sync bf16 (hi/lo split => ~fp32 accuracy), sm_103 baseline.
// ---------------------------------------------------------------------------

#define MROWS 12608
#define DM    768
#define DF    3072
#define SEQ   197
#define NB    64
#define NH    12
#define HD    64
#define NDREL 732

#define TM 128
#define TN 128
#define BK 64

// Scratch
__device__ float g_h  [MROWS * DM];
__device__ float g_hn [MROWS * DM];
__device__ float g_q  [MROWS * DM];
__device__ float g_k  [MROWS * DM];
__device__ float g_v  [MROWS * DM];
__device__ float g_ctx[MROWS * DM];
__device__ float g_f  [MROWS * DF];

// ---------------------------------------------------------------------------
// helpers
// ---------------------------------------------------------------------------
__device__ __forceinline__ uint32_t smem_u32(const void* p) {
    uint32_t a;
    asm("{ .reg .u64 t; cvta.to.shared.u64 t, %1; cvt.u32.u64 %0, t; }"
        : "=r"(a) : "l"(p));
    return a;
}

#define SWZ(o) ((o) ^ (((o) >> 3) & 0x70))

__device__ __forceinline__ void ldm4(uint32_t* r, uint32_t addr) {
    asm volatile("ldmatrix.sync.aligned.m8n8.x4.shared.b16 {%0,%1,%2,%3}, [%4];"
                 : "=r"(r[0]), "=r"(r[1]), "=r"(r[2]), "=r"(r[3]) : "r"(addr));
}
__device__ __forceinline__ void mma16816(float* c, const uint32_t* a,
                                         uint32_t b0, uint32_t b1) {
    asm volatile(
        "mma.sync.aligned.m16n8k16.row.col.f32.bf16.bf16.f32 "
        "{%0,%1,%2,%3}, {%4,%5,%6,%7}, {%8,%9}, {%0,%1,%2,%3};"
        : "+f"(c[0]), "+f"(c[1]), "+f"(c[2]), "+f"(c[3])
        : "r"(a[0]), "r"(a[1]), "r"(a[2]), "r"(a[3]), "r"(b0), "r"(b1));
}

__device__ __forceinline__ uint32_t pkhi(float a, float b, float& ra, float& rb) {
    __nv_bfloat16 ha = __float2bfloat16_rn(a), hb = __float2bfloat16_rn(b);
    ra = a - __bfloat162float(ha);
    rb = b - __bfloat162float(hb);
    return (uint32_t)__bfloat16_as_ushort(ha) |
           ((uint32_t)__bfloat16_as_ushort(hb) << 16);
}
__device__ __forceinline__ uint32_t pklo(float a, float b) {
    return (uint32_t)__bfloat16_as_ushort(__float2bfloat16_rn(a)) |
           ((uint32_t)__bfloat16_as_ushort(__float2bfloat16_rn(b)) << 16);
}

// ldmatrix x4 address: per-lane row (lane&15), k-half select (lane>>4)
__device__ __forceinline__ uint32_t swaddr(uint32_t base, int row, int ks, int lane) {
    uint32_t o = (uint32_t)(row + (lane & 15)) * 128 + (uint32_t)ks * 32 +
                 (uint32_t)((lane >> 4) << 4);
    return base + SWZ(o);
}

// ---------------------------------------------------------------------------
// bf16 hi/lo split GEMM: C[M,N] = epi(A[M,K] @ W[K,N] + bias)
//  mode 0: +bias (may be null); 1: gelu(+bias); 2: res + (x+bias)*lam
//  CTA 128x128, BK=64, 8 warps (each 64m x 32n)
// ---------------------------------------------------------------------------
#define GEMM_SMEM (4 * TM * BK * 2)   // 65536: Ahi, Alo, Bhi, Blo

__global__ void __launch_bounds__(256, 2) mmagemm(
    const float* __restrict__ A, const float* __restrict__ W,
    const float* __restrict__ bias, const float* __restrict__ res,
    const float* __restrict__ lam, float* __restrict__ C,
    int M, int N, int K, int mode)
{
    extern __shared__ char smem[];
    const int AHI = 0;
    const int ALO = TM * BK * 2;
    const int BHI = 2 * TM * BK * 2;
    const int BLO = 3 * TM * BK * 2;

    uint32_t sb = smem_u32(smem);
    const uint32_t sAh = sb + AHI, sAl = sb + ALO, sBh = sb + BHI, sBl = sb + BLO;

    int t = threadIdx.x, wid = t >> 5, lane = t & 31;
    int bm = blockIdx.y * TM, bn = blockIdx.x * TN;

    // A loader mapping: row = t>>1, 8 float4 per thread
    int am = t >> 1, ahalf = t & 1;
    bool mval = (bm + am) < M;
    const float* Arow = A + (size_t)(bm + am) * K;

    // B loader mapping: n = t&127, kh = t>>7 (32 k each)
    int bn_t = t & 127, bkh = t >> 7;
    const float* Wp = W + bn + bn_t;

    // warp tiling: wm in {0,1} (64 rows), wn in {0..3} (32 cols)
    int wm = wid >> 2, wn = wid & 3;
    int rmw = wm * 64;
    int nbw = wn * 32;

    float acc[4][4][4];
    #pragma unroll
    for (int i = 0; i < 4; i++)
        #pragma unroll
        for (int j = 0; j < 4; j++)
            #pragma unroll
            for (int r = 0; r < 4; r++) acc[i][j][r] = 0.f;

    for (int kc = 0; kc < K; kc += BK) {
        // ---- A tile: [128m x 64k] fp32 -> hi/lo bf16, SW128 ----
        #pragma unroll
        for (int j = 0; j < 8; j++) {
            int k4 = ahalf * 8 + j;
            float4 a = mval ? *(const float4*)(Arow + kc + k4 * 4)
                            : make_float4(0.f, 0.f, 0.f, 0.f);
            float l0, l1, l2, l3;
            uint32_t h01 = pkhi(a.x, a.y, l0, l1);
            uint32_t h23 = pkhi(a.z, a.w, l2, l3);
            uint32_t off = SWZ((uint32_t)(am * 128 + k4 * 8));
            *(uint2*)(smem + AHI + off) = make_uint2(h01, h23);
            *(uint2*)(smem + ALO + off) = make_uint2(pklo(l0, l1), pklo(l2, l3));
        }
        // ---- B tile: Bs[n][k] = W[k][n], hi/lo ----
        {
            const float* wp = Wp + (size_t)kc * N;
            #pragma unroll
            for (int kk = bkh * 32; kk < bkh * 32 + 32; kk += 4) {
                float w0 = wp[(size_t)(kk + 0) * N];
                float w1 = wp[(size_t)(kk + 1) * N];
                float w2 = wp[(size_t)(kk + 2) * N];
                float w3 = wp[(size_t)(kk + 3) * N];
                float l0, l1, l2, l3;
                uint32_t h01 = pkhi(w0, w1, l0, l1);
                uint32_t h23 = pkhi(w2, w3, l2, l3);
                uint32_t off = SWZ((uint32_t)(bn_t * 128 + kk * 2));
                *(uint2*)(smem + BHI + off) = make_uint2(h01, h23);
                *(uint2*)(smem + BLO + off) = make_uint2(pklo(l0, l1), pklo(l2, l3));
            }
        }
        __syncthreads();

        // ---- MMA over 4 k16 steps ----
        #pragma unroll
        for (int ks = 0; ks < 4; ks++) {
            uint32_t bh[8], bl[8], a4[4][4];
            #pragma unroll
            for (int j = 0; j < 2; j++) {
                ldm4(&bh[j * 4], swaddr(sBh, nbw + j * 16, ks, lane));
                ldm4(&bl[j * 4], swaddr(sBl, nbw + j * 16, ks, lane));
            }
            #pragma unroll
            for (int mi = 0; mi < 4; mi++)
                ldm4(a4[mi], swaddr(sAh, rmw + mi * 16, ks, lane));
            // hi*hi + hi*lo
            #pragma unroll
            for (int mi = 0; mi < 4; mi++)
                #pragma unroll
                for (int j2 = 0; j2 < 4; j2++) {
                    int base = (j2 >> 1) * 4, sel = j2 & 1;
                    mma16816(acc[mi][j2], a4[mi], bh[base + sel], bh[base + 2 + sel]);
                    mma16816(acc[mi][j2], a4[mi], bl[base + sel], bl[base + 2 + sel]);
                }
            // lo*hi
            #pragma unroll
            for (int mi = 0; mi < 4; mi++)
                ldm4(a4[mi], swaddr(sAl, rmw + mi * 16, ks, lane));
            #pragma unroll
            for (int mi = 0; mi < 4; mi++)
                #pragma unroll
                for (int j2 = 0; j2 < 4; j2++) {
                    int base = (j2 >> 1) * 4, sel = j2 & 1;
                    mma16816(acc[mi][j2], a4[mi], bh[base + sel], bh[base + 2 + sel]);
                }
        }
        __syncthreads();
    }

    // ---- epilogue ----
    int r0 = lane >> 2, c0 = (lane & 3) * 2;
    #pragma unroll
    for (int mi = 0; mi < 4; mi++) {
        #pragma unroll
        for (int j2 = 0; j2 < 4; j2++) {
            int gn = bn + nbw + j2 * 8 + c0;
            float b0 = 0.f, b1 = 0.f;
            if (bias) { b0 = bias[gn]; b1 = bias[gn + 1]; }
            float l0 = 0.f, l1 = 0.f;
            if (mode == 2) { l0 = lam[gn]; l1 = lam[gn + 1]; }
            #pragma unroll
            for (int half = 0; half < 2; half++) {
                int gm = bm + rmw + mi * 16 + r0 + half * 8;
                if (gm >= M) continue;
                float vx = acc[mi][j2][half * 2 + 0] + b0;
                float vy = acc[mi][j2][half * 2 + 1] + b1;
                if (mode == 1) {
                    vx = 0.5f * vx * (1.0f + erff(vx * 0.70710678118654752f));
                    vy = 0.5f * vy * (1.0f + erff(vy * 0.70710678118654752f));
                } else if (mode == 2) {
                    const float2 rr = *(const float2*)(res + (size_t)gm * N + gn);
                    vx = rr.x + vx * l0;
                    vy = rr.y + vy * l1;
                }
                *(float2*)(C + (size_t)gm * N + gn) = make_float2(vx, vy);
            }
        }
    }
}

// ---------------------------------------------------------------------------
// Patch embed
// ---------------------------------------------------------------------------
__global__ void embed_kernel(const float* __restrict__ x, const float* __restrict__ cls,
                             float* __restrict__ h)
{
    int i = blockIdx.x * 256 + threadIdx.x;
    if (i >= MROWS * DM) return;
    int c = i % DM;
    int s = (i / DM) % SEQ;
    int b = i / (DM * SEQ);
    h[i] = (s == 0) ? cls[c] : x[((size_t)(b * 196 + s - 1)) * DM + c];
}

// ---------------------------------------------------------------------------
// LayerNorm
// ---------------------------------------------------------------------------
__global__ void ln_kernel(const float* __restrict__ x, const float* __restrict__ g,
                          const float* __restrict__ bta, float* __restrict__ y)
{
    int row = blockIdx.x;
    const float* xr = x + (size_t)row * DM;
    int t = threadIdx.x;
    float v0 = xr[t], v1 = xr[t + 256], v2 = xr[t + 512];
    __shared__ float sh[8];

    float s = v0 + v1 + v2;
    #pragma unroll
    for (int o = 16; o; o >>= 1) s += __shfl_xor_sync(0xffffffffu, s, o);
    if ((t & 31) == 0) sh[t >> 5] = s;
    __syncthreads();
    if (t == 0) { float tot = 0.f; for (int i = 0; i < 8; i++) tot += sh[i]; sh[0] = tot; }
    __syncthreads();
    float mean = sh[0] * (1.0f / 768.0f);
    __syncthreads();

    float d0 = v0 - mean, d1 = v1 - mean, d2 = v2 - mean;
    s = d0 * d0 + d1 * d1 + d2 * d2;
    #pragma unroll
    for (int o = 16; o; o >>= 1) s += __shfl_xor_sync(0xffffffffu, s, o);
    if ((t & 31) == 0) sh[t >> 5] = s;
    __syncthreads();
    if (t == 0) { float tot = 0.f; for (int i = 0; i < 8; i++) tot += sh[i]; sh[0] = tot; }
    __syncthreads();
    float rstd = rsqrtf(sh[0] * (1.0f / 768.0f) + 1e-12f);

    float* yr = y + (size_t)row * DM;
    yr[t]       = d0 * rstd * g[t]       + bta[t];
    yr[t + 256] = d1 * rstd * g[t + 256] + bta[t + 256];
    yr[t + 512] = d2 * rstd * g[t + 512] + bta[t + 512];
}

// ---------------------------------------------------------------------------
// Attention
// ---------------------------------------------------------------------------
__device__ __forceinline__ int relidx(int q, int k)
{
    if (q == 0 && k == 0) return NDREL - 1;
    if (q == 0)           return NDREL - 3;
    if (k == 0)           return NDREL - 2;
    int p = q - 1, r = k - 1;
    int di = p / 14 - r / 14 + 13;
    int dj = p % 14 - r % 14 + 13;
    return di * 27 + dj;
}

#define KS_PITCH 65
#define ATT_SMEM_FLOATS (2 * SEQ * KS_PITCH + 8 * 64 + 8 * 200)
#define ATT_SMEM_BYTES  (ATT_SMEM_FLOATS * 4)

__global__ void attn_kernel(const float* __restrict__ Q, const float* __restrict__ Kg,
                            const float* __restrict__ Vg, const float* __restrict__ rel,
                            float* __restrict__ ctx)
{
    int h = blockIdx.x, b = blockIdx.y;
    extern __shared__ float sm[];
    float* Ks = sm;
    float* Vs = sm + SEQ * KS_PITCH;
    float* qs = sm + 2 * SEQ * KS_PITCH;
    float* Ps = qs + 8 * 64;

    int t = threadIdx.x;
    for (int idx = t; idx < SEQ * HD; idx += 256) {
        int kk = idx >> 6, d = idx & 63;
        size_t g = (size_t)(b * SEQ + kk) * DM + h * HD + d;
        Ks[kk * KS_PITCH + d] = Kg[g];
        Vs[kk * KS_PITCH + d] = Vg[g];
    }
    __syncthreads();

    int w = t >> 5, lane = t & 31;
    for (int q = w; q < SEQ; q += 8) {
        size_t qbase = (size_t)(b * SEQ + q) * DM + h * HD;
        qs[w * 64 + lane]      = Q[qbase + lane];
        qs[w * 64 + lane + 32] = Q[qbase + lane + 32];
        __syncwarp();

        float s[7];
        float mx = -1e30f;
        #pragma unroll
        for (int j = 0; j < 7; j++) {
            int kk = lane + j * 32;
            float acc = -1e30f;
            if (kk < SEQ) {
                float v = 0.f;
                #pragma unroll
                for (int d = 0; d < HD; d++) v += qs[w * 64 + d] * Ks[kk * KS_PITCH + d];
                acc = v * 0.125f + rel[relidx(q, kk) * NH + h];
            }
            s[j] = acc;
            mx = fmaxf(mx, acc);
        }
        #pragma unroll
        for (int o = 16; o; o >>= 1) mx = fmaxf(mx, __shfl_xor_sync(0xffffffffu, mx, o));

        float sum = 0.f;
        #pragma unroll
        for (int j = 0; j < 7; j++) {
            int kk = lane + j * 32;
            float e = (kk < SEQ) ? expf(s[j] - mx) : 0.f;
            s[j] = e;
            sum += e;
        }
        #pragma unroll
        for (int o = 16; o; o >>= 1) sum += __shfl_xor_sync(0xffffffffu, sum, o);
        float inv = 1.0f / sum;

        #pragma unroll
        for (int j = 0; j < 7; j++) {
            int kk = lane + j * 32;
            if (kk < SEQ) Ps[w * 200 + kk] = s[j] * inv;
        }
        __syncwarp();

        float a0 = 0.f, a1 = 0.f;
        for (int kk = 0; kk < SEQ; kk++) {
            float p = Ps[w * 200 + kk];
            a0 += p * Vs[kk * KS_PITCH + lane];
            a1 += p * Vs[kk * KS_PITCH + lane + 32];
        }
        ctx[qbase + lane]      = a0;
        ctx[qbase + lane + 32] = a1;
        __syncwarp();
    }
}

// ---------------------------------------------------------------------------
// Orchestration
// ---------------------------------------------------------------------------
extern "C" void kernel_launch(void* const* d_in, const int* in_sizes, int n_in,
                              void* d_out, int out_size)
{
    const float* x    = (const float*)d_in[0];
    const float* cls  = (const float*)d_in[1];
    const float* g1   = (const float*)d_in[2];
    const float* b1   = (const float*)d_in[3];
    const float* Wq   = (const float*)d_in[4];
    const float* bq   = (const float*)d_in[5];
    const float* Wk   = (const float*)d_in[6];
    const float* Wv   = (const float*)d_in[7];
    const float* bv   = (const float*)d_in[8];
    const float* rel  = (const float*)d_in[9];
    const float* Wo   = (const float*)d_in[10];
    const float* bo   = (const float*)d_in[11];
    const float* lam1 = (const float*)d_in[12];
    const float* g2   = (const float*)d_in[13];
    const float* b2   = (const float*)d_in[14];
    const float* Wi   = (const float*)d_in[15];
    const float* bi   = (const float*)d_in[16];
    const float* Wmo  = (const float*)d_in[17];
    const float* bmo  = (const float*)d_in[18];
    const float* lam2 = (const float*)d_in[19];

    float *h, *hn, *q, *k, *v, *ctx, *f;
    cudaGetSymbolAddress((void**)&h,   g_h);
    cudaGetSymbolAddress((void**)&hn,  g_hn);
    cudaGetSymbolAddress((void**)&q,   g_q);
    cudaGetSymbolAddress((void**)&k,   g_k);
    cudaGetSymbolAddress((void**)&v,   g_v);
    cudaGetSymbolAddress((void**)&ctx, g_ctx);
    cudaGetSymbolAddress((void**)&f,   g_f);

    cudaFuncSetAttribute(attn_kernel, cudaFuncAttributeMaxDynamicSharedMemorySize,
                         ATT_SMEM_BYTES);
    cudaFuncSetAttribute(mmagemm, cudaFuncAttributeMaxDynamicSharedMemorySize,
                         GEMM_SMEM);

    embed_kernel<<<(MROWS * DM + 255) / 256, 256>>>(x, cls, h);

    int mt = (MROWS + TM - 1) / TM;        // 99
    dim3 g768(DM / TN, mt);                // (6, 99)
    dim3 g3072(DF / TN, mt);               // (24, 99)

    for (int i = 0; i < 3; i++) {
        size_t wo  = (size_t)i * DM * DM;
        size_t wio = (size_t)i * DM * DF;

        ln_kernel<<<MROWS, 256>>>(h, g1 + i * DM, b1 + i * DM, hn);

        mmagemm<<<g768, 256, GEMM_SMEM>>>(hn, Wq + wo, bq + i * DM, nullptr, nullptr, q,
                                          MROWS, DM, DM, 0);
        mmagemm<<<g768, 256, GEMM_SMEM>>>(hn, Wk + wo, nullptr, nullptr, nullptr, k,
                                          MROWS, DM, DM, 0);
        mmagemm<<<g768, 256, GEMM_SMEM>>>(hn, Wv + wo, bv + i * DM, nullptr, nullptr, v,
                                          MROWS, DM, DM, 0);

        attn_kernel<<<dim3(NH, NB), 256, ATT_SMEM_BYTES>>>(
            q, k, v, rel + (size_t)i * NDREL * NH, ctx);

        mmagemm<<<g768, 256, GEMM_SMEM>>>(ctx, Wo + wo, bo + i * DM, h, lam1 + i * DM, h,
                                          MROWS, DM, DM, 2);

        ln_kernel<<<MROWS, 256>>>(h, g2 + i * DM, b2 + i * DM, hn);

        mmagemm<<<g3072, 256, GEMM_SMEM>>>(hn, Wi + wio, bi + i * DF, nullptr, nullptr, f,
                                           MROWS, DF, DM, 1);

        mmagemm<<<g768, 256, GEMM_SMEM>>>(f, Wmo + wio, bmo + i * DM, h, lam2 + i * DM,
                                          (i == 2) ? (float*)d_out : h,
                                          MROWS, DM, DF, 2);
    }
}

// round 5
// speedup vs baseline: 2.3911x; 1.2057x over previous
#include <cuda_runtime.h>
#include <cuda_bf16.h>
#include <math.h>
#include <stdint.h>

// ---------------------------------------------------------------------------
// BEiT encoder: B=64, S=197, DM=768, H=12, D=64, DF=3072, L=3
// GEMMs: mma.sync bf16 hi/lo split, cp.async double-buffered, pre-split inputs.
// ---------------------------------------------------------------------------

#define MROWS 12608
#define DM    768
#define DF    3072
#define SEQ   197
#define NB    64
#define NH    12
#define HD    64
#define NDREL 732

#define TM 128
#define TN 128
#define BK 64

typedef __nv_bfloat16 bf16;

// fp32 scratch
__device__ float g_h  [MROWS * DM];
__device__ float g_q  [MROWS * DM];
__device__ float g_k  [MROWS * DM];
__device__ float g_v  [MROWS * DM];
// bf16 hi/lo activation planes
__device__ bf16 g_hn_hi [MROWS * DM];
__device__ bf16 g_hn_lo [MROWS * DM];
__device__ bf16 g_ctx_hi[MROWS * DM];
__device__ bf16 g_ctx_lo[MROWS * DM];
__device__ bf16 g_f_hi  [MROWS * DF];
__device__ bf16 g_f_lo  [MROWS * DF];
// transposed weight planes [N][K]
__device__ bf16 g_wA_hi [3 * 4 * DM * DM];   // Wq,Wk,Wv,Wo per layer
__device__ bf16 g_wA_lo [3 * 4 * DM * DM];
__device__ bf16 g_wi_hi [3 * DF * DM];
__device__ bf16 g_wi_lo [3 * DF * DM];
__device__ bf16 g_wmo_hi[3 * DM * DF];
__device__ bf16 g_wmo_lo[3 * DM * DF];

// ---------------------------------------------------------------------------
// helpers
// ---------------------------------------------------------------------------
__device__ __forceinline__ uint32_t smem_u32(const void* p) {
    uint32_t a;
    asm("{ .reg .u64 t; cvta.to.shared.u64 t, %1; cvt.u32.u64 %0, t; }"
        : "=r"(a) : "l"(p));
    return a;
}

#define SWZ(o) ((o) ^ (((o) >> 3) & 0x70))

__device__ __forceinline__ void ldm4(uint32_t* r, uint32_t addr) {
    asm volatile("ldmatrix.sync.aligned.m8n8.x4.shared.b16 {%0,%1,%2,%3}, [%4];"
                 : "=r"(r[0]), "=r"(r[1]), "=r"(r[2]), "=r"(r[3]) : "r"(addr));
}
__device__ __forceinline__ void mma16816(float* c, const uint32_t* a,
                                         uint32_t b0, uint32_t b1) {
    asm volatile(
        "mma.sync.aligned.m16n8k16.row.col.f32.bf16.bf16.f32 "
        "{%0,%1,%2,%3}, {%4,%5,%6,%7}, {%8,%9}, {%0,%1,%2,%3};"
        : "+f"(c[0]), "+f"(c[1]), "+f"(c[2]), "+f"(c[3])
        : "r"(a[0]), "r"(a[1]), "r"(a[2]), "r"(a[3]), "r"(b0), "r"(b1));
}
__device__ __forceinline__ void cpa16(uint32_t dst, const void* src, int sz) {
    asm volatile("cp.async.ca.shared.global [%0], [%1], 16, %2;"
                 :: "r"(dst), "l"(src), "r"(sz));
}
#define CP_COMMIT() asm volatile("cp.async.commit_group;" ::: "memory")
#define CP_WAIT1()  asm volatile("cp.async.wait_group 1;" ::: "memory")

__device__ __forceinline__ uint32_t swaddr(uint32_t base, int row, int ks, int lane) {
    uint32_t o = (uint32_t)(row + (lane & 15)) * 128 + (uint32_t)ks * 32 +
                 (uint32_t)((lane >> 4) << 4);
    return base + SWZ(o);
}
__device__ __forceinline__ void split2(float a, float b, uint32_t& hi, uint32_t& lo) {
    bf16 ha = __float2bfloat16_rn(a), hb = __float2bfloat16_rn(b);
    bf16 la = __float2bfloat16_rn(a - __bfloat162float(ha));
    bf16 lb = __float2bfloat16_rn(b - __bfloat162float(hb));
    hi = (uint32_t)__bfloat16_as_ushort(ha) | ((uint32_t)__bfloat16_as_ushort(hb) << 16);
    lo = (uint32_t)__bfloat16_as_ushort(la) | ((uint32_t)__bfloat16_as_ushort(lb) << 16);
}

// ---------------------------------------------------------------------------
// Weight transpose + split: W[K][N] fp32 -> out_hi/lo[N][K] bf16
// ---------------------------------------------------------------------------
__global__ void convw(const float* __restrict__ W, bf16* __restrict__ hi,
                      bf16* __restrict__ lo, int K, int N)
{
    __shared__ float tile[32][33];
    int k0 = blockIdx.y * 32, n0 = blockIdx.x * 32;
    int tx = threadIdx.x, ty = threadIdx.y;
    #pragma unroll
    for (int i = ty; i < 32; i += 8)
        tile[i][tx] = W[(size_t)(k0 + i) * N + n0 + tx];
    __syncthreads();
    #pragma unroll
    for (int i = ty; i < 32; i += 8) {
        float v = tile[tx][i];                   // k = k0+tx, n = n0+i
        bf16 h = __float2bfloat16_rn(v);
        size_t o = (size_t)(n0 + i) * K + k0 + tx;
        hi[o] = h;
        lo[o] = __float2bfloat16_rn(v - __bfloat162float(h));
    }
}

// ---------------------------------------------------------------------------
// GEMM: C = epi(A @ B^T), A planes [M][K], B planes [N][K] (bf16 hi/lo)
//  mode 0: fp32 C = v + bias ; mode 1: gelu -> Chi/Clo planes ;
//  mode 2: fp32 C = res + (v + bias)*lam
// ---------------------------------------------------------------------------
#define GSTAGE    65536
#define GEMM_SMEM (2 * GSTAGE)

__global__ void __launch_bounds__(256, 1) mmagemm(
    const bf16* __restrict__ Ahi, const bf16* __restrict__ Alo,
    const bf16* __restrict__ Bhi, const bf16* __restrict__ Blo,
    const float* __restrict__ bias, const float* __restrict__ res,
    const float* __restrict__ lam, float* __restrict__ C,
    bf16* __restrict__ Chi, bf16* __restrict__ Clo,
    int M, int N, int K, int mode)
{
    extern __shared__ char smem[];
    uint32_t sb = smem_u32(smem);

    int t = threadIdx.x, wid = t >> 5, lane = t & 31;
    int bm = blockIdx.y * TM, bn = blockIdx.x * TN;

    int wm = wid >> 2, wn = wid & 3;
    int rmw = wm * 64, nbw = wn * 32;

    // loader: 4 chunk-groups per plane, chunk ci = j*256+t, r=ci>>3, c=ci&7
    int rr[4], cc[4];
    uint32_t dsw[4];
    #pragma unroll
    for (int j = 0; j < 4; j++) {
        int ci = j * 256 + t;
        rr[j] = ci >> 3; cc[j] = ci & 7;
        dsw[j] = SWZ((uint32_t)(rr[j] * 128 + cc[j] * 16));
    }

    float acc[4][4][4];
    #pragma unroll
    for (int i = 0; i < 4; i++)
        #pragma unroll
        for (int j = 0; j < 4; j++)
            #pragma unroll
            for (int r = 0; r < 4; r++) acc[i][j][r] = 0.f;

    const int nk = K / BK;

    // prologue: stage 0
    {
        uint32_t s0 = sb;
        #pragma unroll
        for (int j = 0; j < 4; j++) {
            int r = rr[j], c = cc[j];
            int va = (bm + r) < M ? 16 : 0;
            size_t ao = (size_t)(bm + r) * K + c * 8;
            size_t bo = (size_t)(bn + r) * K + c * 8;
            cpa16(s0 + dsw[j],          Ahi + ao, va);
            cpa16(s0 + 16384 + dsw[j],  Alo + ao, va);
            cpa16(s0 + 32768 + dsw[j],  Bhi + bo, 16);
            cpa16(s0 + 49152 + dsw[j],  Blo + bo, 16);
        }
        CP_COMMIT();
    }

    for (int ki = 0; ki < nk; ki++) {
        if (ki + 1 < nk) {
            uint32_t sn = sb + ((ki + 1) & 1) * GSTAGE;
            int kc = (ki + 1) * BK;
            #pragma unroll
            for (int j = 0; j < 4; j++) {
                int r = rr[j], c = cc[j];
                int va = (bm + r) < M ? 16 : 0;
                size_t ao = (size_t)(bm + r) * K + kc + c * 8;
                size_t bo = (size_t)(bn + r) * K + kc + c * 8;
                cpa16(sn + dsw[j],          Ahi + ao, va);
                cpa16(sn + 16384 + dsw[j],  Alo + ao, va);
                cpa16(sn + 32768 + dsw[j],  Bhi + bo, 16);
                cpa16(sn + 49152 + dsw[j],  Blo + bo, 16);
            }
        }
        CP_COMMIT();
        CP_WAIT1();
        __syncthreads();

        uint32_t sAh = sb + (ki & 1) * GSTAGE;
        uint32_t sAl = sAh + 16384, sBh = sAh + 32768, sBl = sAh + 49152;

        #pragma unroll
        for (int ks = 0; ks < 4; ks++) {
            uint32_t bh[8], bl[8], a4[4][4];
            #pragma unroll
            for (int j = 0; j < 2; j++) {
                ldm4(&bh[j * 4], swaddr(sBh, nbw + j * 16, ks, lane));
                ldm4(&bl[j * 4], swaddr(sBl, nbw + j * 16, ks, lane));
            }
            #pragma unroll
            for (int mi = 0; mi < 4; mi++)
                ldm4(a4[mi], swaddr(sAh, rmw + mi * 16, ks, lane));
            #pragma unroll
            for (int mi = 0; mi < 4; mi++)
                #pragma unroll
                for (int j2 = 0; j2 < 4; j2++) {
                    int base = (j2 >> 1) * 4, sel = j2 & 1;
                    mma16816(acc[mi][j2], a4[mi], bh[base + sel], bh[base + 2 + sel]);
                    mma16816(acc[mi][j2], a4[mi], bl[base + sel], bl[base + 2 + sel]);
                }
            #pragma unroll
            for (int mi = 0; mi < 4; mi++)
                ldm4(a4[mi], swaddr(sAl, rmw + mi * 16, ks, lane));
            #pragma unroll
            for (int mi = 0; mi < 4; mi++)
                #pragma unroll
                for (int j2 = 0; j2 < 4; j2++) {
                    int base = (j2 >> 1) * 4, sel = j2 & 1;
                    mma16816(acc[mi][j2], a4[mi], bh[base + sel], bh[base + 2 + sel]);
                }
        }
        __syncthreads();
    }

    // ---- epilogue ----
    int r0 = lane >> 2, c0 = (lane & 3) * 2;
    #pragma unroll
    for (int mi = 0; mi < 4; mi++) {
        #pragma unroll
        for (int j2 = 0; j2 < 4; j2++) {
            int gn = bn + nbw + j2 * 8 + c0;
            float b0 = 0.f, b1 = 0.f;
            if (bias) { b0 = bias[gn]; b1 = bias[gn + 1]; }
            float l0 = 0.f, l1 = 0.f;
            if (mode == 2) { l0 = lam[gn]; l1 = lam[gn + 1]; }
            #pragma unroll
            for (int half = 0; half < 2; half++) {
                int gm = bm + rmw + mi * 16 + r0 + half * 8;
                if (gm >= M) continue;
                float vx = acc[mi][j2][half * 2 + 0] + b0;
                float vy = acc[mi][j2][half * 2 + 1] + b1;
                if (mode == 1) {
                    vx = 0.5f * vx * (1.0f + erff(vx * 0.70710678118654752f));
                    vy = 0.5f * vy * (1.0f + erff(vy * 0.70710678118654752f));
                    uint32_t hi, lo;
                    split2(vx, vy, hi, lo);
                    size_t o = (size_t)gm * N + gn;
                    *(uint32_t*)(Chi + o) = hi;
                    *(uint32_t*)(Clo + o) = lo;
                } else {
                    if (mode == 2) {
                        const float2 rv = *(const float2*)(res + (size_t)gm * N + gn);
                        vx = rv.x + vx * l0;
                        vy = rv.y + vy * l1;
                    }
                    *(float2*)(C + (size_t)gm * N + gn) = make_float2(vx, vy);
                }
            }
        }
    }
}

// ---------------------------------------------------------------------------
// Patch embed
// ---------------------------------------------------------------------------
__global__ void embed_kernel(const float* __restrict__ x, const float* __restrict__ cls,
                             float* __restrict__ h)
{
    int i = blockIdx.x * 256 + threadIdx.x;
    if (i >= MROWS * DM) return;
    int c = i % DM;
    int s = (i / DM) % SEQ;
    int b = i / (DM * SEQ);
    h[i] = (s == 0) ? cls[c] : x[((size_t)(b * 196 + s - 1)) * DM + c];
}

// ---------------------------------------------------------------------------
// LayerNorm -> bf16 hi/lo planes
// ---------------------------------------------------------------------------
__global__ void ln_kernel(const float* __restrict__ x, const float* __restrict__ g,
                          const float* __restrict__ bta,
                          bf16* __restrict__ yhi, bf16* __restrict__ ylo)
{
    int row = blockIdx.x;
    const float* xr = x + (size_t)row * DM;
    int t = threadIdx.x;
    float v0 = xr[t], v1 = xr[t + 256], v2 = xr[t + 512];
    __shared__ float sh[8];

    float s = v0 + v1 + v2;
    #pragma unroll
    for (int o = 16; o; o >>= 1) s += __shfl_xor_sync(0xffffffffu, s, o);
    if ((t & 31) == 0) sh[t >> 5] = s;
    __syncthreads();
    if (t == 0) { float tot = 0.f; for (int i = 0; i < 8; i++) tot += sh[i]; sh[0] = tot; }
    __syncthreads();
    float mean = sh[0] * (1.0f / 768.0f);
    __syncthreads();

    float d0 = v0 - mean, d1 = v1 - mean, d2 = v2 - mean;
    s = d0 * d0 + d1 * d1 + d2 * d2;
    #pragma unroll
    for (int o = 16; o; o >>= 1) s += __shfl_xor_sync(0xffffffffu, s, o);
    if ((t & 31) == 0) sh[t >> 5] = s;
    __syncthreads();
    if (t == 0) { float tot = 0.f; for (int i = 0; i < 8; i++) tot += sh[i]; sh[0] = tot; }
    __syncthreads();
    float rstd = rsqrtf(sh[0] * (1.0f / 768.0f) + 1e-12f);

    size_t base = (size_t)row * DM;
    #pragma unroll
    for (int j = 0; j < 3; j++) {
        int col = t + j * 256;
        float d = (j == 0) ? d0 : (j == 1) ? d1 : d2;
        float v = d * rstd * g[col] + bta[col];
        bf16 h = __float2bfloat16_rn(v);
        yhi[base + col] = h;
        ylo[base + col] = __float2bfloat16_rn(v - __bfloat162float(h));
    }
}

// ---------------------------------------------------------------------------
// Attention -> bf16 hi/lo ctx planes
// ---------------------------------------------------------------------------
__device__ __forceinline__ int relidx(int q, int k)
{
    if (q == 0 && k == 0) return NDREL - 1;
    if (q == 0)           return NDREL - 3;
    if (k == 0)           return NDREL - 2;
    int p = q - 1, r = k - 1;
    int di = p / 14 - r / 14 + 13;
    int dj = p % 14 - r % 14 + 13;
    return di * 27 + dj;
}

#define KS_PITCH 65
#define ATT_SMEM_FLOATS (2 * SEQ * KS_PITCH + 8 * 64 + 8 * 200)
#define ATT_SMEM_BYTES  (ATT_SMEM_FLOATS * 4)

__global__ void attn_kernel(const float* __restrict__ Q, const float* __restrict__ Kg,
                            const float* __restrict__ Vg, const float* __restrict__ rel,
                            bf16* __restrict__ chi, bf16* __restrict__ clo)
{
    int h = blockIdx.x, b = blockIdx.y;
    extern __shared__ float sm[];
    float* Ks = sm;
    float* Vs = sm + SEQ * KS_PITCH;
    float* qs = sm + 2 * SEQ * KS_PITCH;
    float* Ps = qs + 8 * 64;

    int t = threadIdx.x;
    for (int idx = t; idx < SEQ * HD; idx += 256) {
        int kk = idx >> 6, d = idx & 63;
        size_t g = (size_t)(b * SEQ + kk) * DM + h * HD + d;
        Ks[kk * KS_PITCH + d] = Kg[g];
        Vs[kk * KS_PITCH + d] = Vg[g];
    }
    __syncthreads();

    int w = t >> 5, lane = t & 31;
    for (int q = w; q < SEQ; q += 8) {
        size_t qbase = (size_t)(b * SEQ + q) * DM + h * HD;
        qs[w * 64 + lane]      = Q[qbase + lane];
        qs[w * 64 + lane + 32] = Q[qbase + lane + 32];
        __syncwarp();

        float s[7];
        float mx = -1e30f;
        #pragma unroll
        for (int j = 0; j < 7; j++) {
            int kk = lane + j * 32;
            float acc = -1e30f;
            if (kk < SEQ) {
                float v = 0.f;
                #pragma unroll
                for (int d = 0; d < HD; d++) v += qs[w * 64 + d] * Ks[kk * KS_PITCH + d];
                acc = v * 0.125f + rel[relidx(q, kk) * NH + h];
            }
            s[j] = acc;
            mx = fmaxf(mx, acc);
        }
        #pragma unroll
        for (int o = 16; o; o >>= 1) mx = fmaxf(mx, __shfl_xor_sync(0xffffffffu, mx, o));

        float sum = 0.f;
        #pragma unroll
        for (int j = 0; j < 7; j++) {
            int kk = lane + j * 32;
            float e = (kk < SEQ) ? expf(s[j] - mx) : 0.f;
            s[j] = e;
            sum += e;
        }
        #pragma unroll
        for (int o = 16; o; o >>= 1) sum += __shfl_xor_sync(0xffffffffu, sum, o);
        float inv = 1.0f / sum;

        #pragma unroll
        for (int j = 0; j < 7; j++) {
            int kk = lane + j * 32;
            if (kk < SEQ) Ps[w * 200 + kk] = s[j] * inv;
        }
        __syncwarp();

        float a0 = 0.f, a1 = 0.f;
        for (int kk = 0; kk < SEQ; kk++) {
            float p = Ps[w * 200 + kk];
            a0 += p * Vs[kk * KS_PITCH + lane];
            a1 += p * Vs[kk * KS_PITCH + lane + 32];
        }
        bf16 h0 = __float2bfloat16_rn(a0);
        bf16 h1 = __float2bfloat16_rn(a1);
        chi[qbase + lane]      = h0;
        chi[qbase + lane + 32] = h1;
        clo[qbase + lane]      = __float2bfloat16_rn(a0 - __bfloat162float(h0));
        clo[qbase + lane + 32] = __float2bfloat16_rn(a1 - __bfloat162float(h1));
        __syncwarp();
    }
}

// ---------------------------------------------------------------------------
// Orchestration
// ---------------------------------------------------------------------------
extern "C" void kernel_launch(void* const* d_in, const int* in_sizes, int n_in,
                              void* d_out, int out_size)
{
    const float* x    = (const float*)d_in[0];
    const float* cls  = (const float*)d_in[1];
    const float* g1   = (const float*)d_in[2];
    const float* b1   = (const float*)d_in[3];
    const float* Wq   = (const float*)d_in[4];
    const float* bq   = (const float*)d_in[5];
    const float* Wk   = (const float*)d_in[6];
    const float* Wv   = (const float*)d_in[7];
    const float* bv   = (const float*)d_in[8];
    const float* rel  = (const float*)d_in[9];
    const float* Wo   = (const float*)d_in[10];
    const float* bo   = (const float*)d_in[11];
    const float* lam1 = (const float*)d_in[12];
    const float* g2   = (const float*)d_in[13];
    const float* b2   = (const float*)d_in[14];
    const float* Wi   = (const float*)d_in[15];
    const float* bi   = (const float*)d_in[16];
    const float* Wmo  = (const float*)d_in[17];
    const float* bmo  = (const float*)d_in[18];
    const float* lam2 = (const float*)d_in[19];

    float *h, *q, *k, *v;
    bf16 *hnh, *hnl, *cth, *ctl, *fh, *fl;
    bf16 *wAh, *wAl, *wih, *wil, *wmh, *wml;
    cudaGetSymbolAddress((void**)&h,   g_h);
    cudaGetSymbolAddress((void**)&q,   g_q);
    cudaGetSymbolAddress((void**)&k,   g_k);
    cudaGetSymbolAddress((void**)&v,   g_v);
    cudaGetSymbolAddress((void**)&hnh, g_hn_hi);
    cudaGetSymbolAddress((void**)&hnl, g_hn_lo);
    cudaGetSymbolAddress((void**)&cth, g_ctx_hi);
    cudaGetSymbolAddress((void**)&ctl, g_ctx_lo);
    cudaGetSymbolAddress((void**)&fh,  g_f_hi);
    cudaGetSymbolAddress((void**)&fl,  g_f_lo);
    cudaGetSymbolAddress((void**)&wAh, g_wA_hi);
    cudaGetSymbolAddress((void**)&wAl, g_wA_lo);
    cudaGetSymbolAddress((void**)&wih, g_wi_hi);
    cudaGetSymbolAddress((void**)&wil, g_wi_lo);
    cudaGetSymbolAddress((void**)&wmh, g_wmo_hi);
    cudaGetSymbolAddress((void**)&wml, g_wmo_lo);

    cudaFuncSetAttribute(attn_kernel, cudaFuncAttributeMaxDynamicSharedMemorySize,
                         ATT_SMEM_BYTES);
    cudaFuncSetAttribute(mmagemm, cudaFuncAttributeMaxDynamicSharedMemorySize,
                         GEMM_SMEM);

    // weight conversion (transpose + hi/lo split)
    dim3 cb(32, 8);
    for (int l = 0; l < 3; l++) {
        size_t wo  = (size_t)l * DM * DM;
        size_t wio = (size_t)l * DM * DF;
        convw<<<dim3(DM / 32, DM / 32), cb>>>(Wq + wo, wAh + (l * 4 + 0) * (size_t)DM * DM,
                                              wAl + (l * 4 + 0) * (size_t)DM * DM, DM, DM);
        convw<<<dim3(DM / 32, DM / 32), cb>>>(Wk + wo, wAh + (l * 4 + 1) * (size_t)DM * DM,
                                              wAl + (l * 4 + 1) * (size_t)DM * DM, DM, DM);
        convw<<<dim3(DM / 32, DM / 32), cb>>>(Wv + wo, wAh + (l * 4 + 2) * (size_t)DM * DM,
                                              wAl + (l * 4 + 2) * (size_t)DM * DM, DM, DM);
        convw<<<dim3(DM / 32, DM / 32), cb>>>(Wo + wo, wAh + (l * 4 + 3) * (size_t)DM * DM,
                                              wAl + (l * 4 + 3) * (size_t)DM * DM, DM, DM);
        convw<<<dim3(DF / 32, DM / 32), cb>>>(Wi + wio, wih + (size_t)l * DF * DM,
                                              wil + (size_t)l * DF * DM, DM, DF);
        convw<<<dim3(DM / 32, DF / 32), cb>>>(Wmo + wio, wmh + (size_t)l * DM * DF,
                                              wml + (size_t)l * DM * DF, DF, DM);
    }

    embed_kernel<<<(MROWS * DM + 255) / 256, 256>>>(x, cls, h);

    int mt = (MROWS + TM - 1) / TM;        // 99
    dim3 g768(DM / TN, mt);
    dim3 g3072(DF / TN, mt);

    for (int l = 0; l < 3; l++) {
        bf16* wq_h = wAh + (size_t)(l * 4 + 0) * DM * DM;
        bf16* wq_l = wAl + (size_t)(l * 4 + 0) * DM * DM;
        bf16* wk_h = wAh + (size_t)(l * 4 + 1) * DM * DM;
        bf16* wk_l = wAl + (size_t)(l * 4 + 1) * DM * DM;
        bf16* wv_h = wAh + (size_t)(l * 4 + 2) * DM * DM;
        bf16* wv_l = wAl + (size_t)(l * 4 + 2) * DM * DM;
        bf16* wo_h = wAh + (size_t)(l * 4 + 3) * DM * DM;
        bf16* wo_l = wAl + (size_t)(l * 4 + 3) * DM * DM;
        bf16* wi_h = wih + (size_t)l * DF * DM;
        bf16* wi_l = wil + (size_t)l * DF * DM;
        bf16* wm_h = wmh + (size_t)l * DM * DF;
        bf16* wm_l = wml + (size_t)l * DM * DF;

        ln_kernel<<<MROWS, 256>>>(h, g1 + l * DM, b1 + l * DM, hnh, hnl);

        mmagemm<<<g768, 256, GEMM_SMEM>>>(hnh, hnl, wq_h, wq_l, bq + l * DM,
                                          nullptr, nullptr, q, nullptr, nullptr,
                                          MROWS, DM, DM, 0);
        mmagemm<<<g768, 256, GEMM_SMEM>>>(hnh, hnl, wk_h, wk_l, nullptr,
                                          nullptr, nullptr, k, nullptr, nullptr,
                                          MROWS, DM, DM, 0);
        mmagemm<<<g768, 256, GEMM_SMEM>>>(hnh, hnl, wv_h, wv_l, bv + l * DM,
                                          nullptr, nullptr, v, nullptr, nullptr,
                                          MROWS, DM, DM, 0);

        attn_kernel<<<dim3(NH, NB), 256, ATT_SMEM_BYTES>>>(
            q, k, v, rel + (size_t)l * NDREL * NH, cth, ctl);

        mmagemm<<<g768, 256, GEMM_SMEM>>>(cth, ctl, wo_h, wo_l, bo + l * DM,
                                          h, lam1 + l * DM, h, nullptr, nullptr,
                                          MROWS, DM, DM, 2);

        ln_kernel<<<MROWS, 256>>>(h, g2 + l * DM, b2 + l * DM, hnh, hnl);

        mmagemm<<<g3072, 256, GEMM_SMEM>>>(hnh, hnl, wi_h, wi_l, bi + l * DF,
                                           nullptr, nullptr, nullptr, fh, fl,
                                           MROWS, DF, DM, 1);

        mmagemm<<<g768, 256, GEMM_SMEM>>>(fh, fl, wm_h, wm_l, bmo + l * DM,
                                          h, lam2 + l * DM,
                                          (l == 2) ? (float*)d_out : h, nullptr, nullptr,
                                          MROWS, DM, DF, 2);
    }
}

// round 6
// speedup vs baseline: 2.4902x; 1.0414x over previous
#include <cuda_runtime.h>
#include <cuda_bf16.h>
#include <math.h>
#include <stdint.h>

// ---------------------------------------------------------------------------
// BEiT encoder: B=64, S=197, DM=768, H=12, D=64, DF=3072, L=3
// GEMMs: mma.sync bf16 hi/lo split, cp.async double-buffered, 128x64 tiles,
// 2 CTAs/SM. QKV fused into one GEMM (N=2304).
// ---------------------------------------------------------------------------

#define MROWS 12608
#define DM    768
#define DF    3072
#define NQKV  2304
#define SEQ   197
#define NB    64
#define NH    12
#define HD    64
#define NDREL 732

#define TM 128
#define TN 64
#define BK 64

typedef __nv_bfloat16 bf16;

// fp32 scratch
__device__ float g_h   [MROWS * DM];
__device__ float g_qkv [MROWS * NQKV];
__device__ float g_bqkv[NQKV];
// bf16 hi/lo activation planes
__device__ bf16 g_hn_hi [MROWS * DM];
__device__ bf16 g_hn_lo [MROWS * DM];
__device__ bf16 g_ctx_hi[MROWS * DM];
__device__ bf16 g_ctx_lo[MROWS * DM];
__device__ bf16 g_f_hi  [MROWS * DF];
__device__ bf16 g_f_lo  [MROWS * DF];
// transposed weight planes [N][K]
__device__ bf16 g_wqkv_hi[3 * NQKV * DM];
__device__ bf16 g_wqkv_lo[3 * NQKV * DM];
__device__ bf16 g_wo_hi  [3 * DM * DM];
__device__ bf16 g_wo_lo  [3 * DM * DM];
__device__ bf16 g_wi_hi  [3 * DF * DM];
__device__ bf16 g_wi_lo  [3 * DF * DM];
__device__ bf16 g_wmo_hi [3 * DM * DF];
__device__ bf16 g_wmo_lo [3 * DM * DF];

// ---------------------------------------------------------------------------
// helpers
// ---------------------------------------------------------------------------
__device__ __forceinline__ uint32_t smem_u32(const void* p) {
    uint32_t a;
    asm("{ .reg .u64 t; cvta.to.shared.u64 t, %1; cvt.u32.u64 %0, t; }"
        : "=r"(a) : "l"(p));
    return a;
}

#define SWZ(o) ((o) ^ (((o) >> 3) & 0x70))

__device__ __forceinline__ void ldm4(uint32_t* r, uint32_t addr) {
    asm volatile("ldmatrix.sync.aligned.m8n8.x4.shared.b16 {%0,%1,%2,%3}, [%4];"
                 : "=r"(r[0]), "=r"(r[1]), "=r"(r[2]), "=r"(r[3]) : "r"(addr));
}
__device__ __forceinline__ void mma16816(float* c, const uint32_t* a,
                                         uint32_t b0, uint32_t b1) {
    asm volatile(
        "mma.sync.aligned.m16n8k16.row.col.f32.bf16.bf16.f32 "
        "{%0,%1,%2,%3}, {%4,%5,%6,%7}, {%8,%9}, {%0,%1,%2,%3};"
        : "+f"(c[0]), "+f"(c[1]), "+f"(c[2]), "+f"(c[3])
        : "r"(a[0]), "r"(a[1]), "r"(a[2]), "r"(a[3]), "r"(b0), "r"(b1));
}
__device__ __forceinline__ void cpa16(uint32_t dst, const void* src, int sz) {
    asm volatile("cp.async.ca.shared.global [%0], [%1], 16, %2;"
                 :: "r"(dst), "l"(src), "r"(sz));
}
#define CP_COMMIT() asm volatile("cp.async.commit_group;" ::: "memory")
#define CP_WAIT1()  asm volatile("cp.async.wait_group 1;" ::: "memory")

__device__ __forceinline__ uint32_t swaddr(uint32_t base, int row, int ks, int lane) {
    uint32_t o = (uint32_t)(row + (lane & 15)) * 128 + (uint32_t)ks * 32 +
                 (uint32_t)((lane >> 4) << 4);
    return base + SWZ(o);
}
__device__ __forceinline__ void split2(float a, float b, uint32_t& hi, uint32_t& lo) {
    bf16 ha = __float2bfloat16_rn(a), hb = __float2bfloat16_rn(b);
    bf16 la = __float2bfloat16_rn(a - __bfloat162float(ha));
    bf16 lb = __float2bfloat16_rn(b - __bfloat162float(hb));
    hi = (uint32_t)__bfloat16_as_ushort(ha) | ((uint32_t)__bfloat16_as_ushort(hb) << 16);
    lo = (uint32_t)__bfloat16_as_ushort(la) | ((uint32_t)__bfloat16_as_ushort(lb) << 16);
}

// ---------------------------------------------------------------------------
// Weight transpose + split: W[K][N] fp32 -> out_hi/lo[N][K] bf16
// ---------------------------------------------------------------------------
__global__ void convw(const float* __restrict__ W, bf16* __restrict__ hi,
                      bf16* __restrict__ lo, int K, int N)
{
    __shared__ float tile[32][33];
    int k0 = blockIdx.y * 32, n0 = blockIdx.x * 32;
    int tx = threadIdx.x, ty = threadIdx.y;
    #pragma unroll
    for (int i = ty; i < 32; i += 8)
        tile[i][tx] = W[(size_t)(k0 + i) * N + n0 + tx];
    __syncthreads();
    #pragma unroll
    for (int i = ty; i < 32; i += 8) {
        float v = tile[tx][i];
        bf16 h = __float2bfloat16_rn(v);
        size_t o = (size_t)(n0 + i) * K + k0 + tx;
        hi[o] = h;
        lo[o] = __float2bfloat16_rn(v - __bfloat162float(h));
    }
}

__global__ void mkbias(const float* __restrict__ bq, const float* __restrict__ bv,
                       float* __restrict__ out)
{
    int i = blockIdx.x * 256 + threadIdx.x;
    if (i >= NQKV) return;
    out[i] = (i < DM) ? bq[i] : (i < 2 * DM) ? 0.f : bv[i - 2 * DM];
}

// ---------------------------------------------------------------------------
// GEMM: C = epi(A @ B^T), A planes [M][K], B planes [N][K] (bf16 hi/lo)
//  mode 0: fp32 C = v + bias ; mode 1: gelu -> Chi/Clo planes ;
//  mode 2: fp32 C = res + (v + bias)*lam
//  CTA tile 128x64, BK=64, double-buffered cp.async, 8 warps (32x32 each)
// ---------------------------------------------------------------------------
#define GSTAGE    49152
#define GEMM_SMEM (2 * GSTAGE)   // 96 KB -> 2 CTAs/SM

__global__ void __launch_bounds__(256, 2) mmagemm(
    const bf16* __restrict__ Ahi, const bf16* __restrict__ Alo,
    const bf16* __restrict__ Bhi, const bf16* __restrict__ Blo,
    const float* __restrict__ bias, const float* __restrict__ res,
    const float* __restrict__ lam, float* __restrict__ C,
    bf16* __restrict__ Chi, bf16* __restrict__ Clo,
    int M, int N, int K, int mode)
{
    extern __shared__ char smem[];
    uint32_t sb = smem_u32(smem);

    int t = threadIdx.x, wid = t >> 5, lane = t & 31;
    int bm = blockIdx.y * TM, bn = blockIdx.x * TN;

    int wm = wid >> 1, wn = wid & 1;       // 4 x 2 warps
    int rmw = wm * 32, nbw = wn * 32;

    // A loaders: 4 chunks/thread; B loaders: 2 chunks/thread
    int ar[4], bw_r[2];
    uint32_t adsw[4], bdsw[2];
    #pragma unroll
    for (int j = 0; j < 4; j++) {
        int ci = j * 256 + t;
        ar[j] = ci >> 3;
        adsw[j] = SWZ((uint32_t)(ar[j] * 128 + (ci & 7) * 16));
    }
    #pragma unroll
    for (int j = 0; j < 2; j++) {
        int ci = j * 256 + t;
        bw_r[j] = ci >> 3;
        bdsw[j] = SWZ((uint32_t)(bw_r[j] * 128 + (ci & 7) * 16));
    }

    float acc[2][4][4];
    #pragma unroll
    for (int i = 0; i < 2; i++)
        #pragma unroll
        for (int j = 0; j < 4; j++)
            #pragma unroll
            for (int r = 0; r < 4; r++) acc[i][j][r] = 0.f;

    const int nk = K / BK;

    // prologue
    {
        uint32_t s0 = sb;
        #pragma unroll
        for (int j = 0; j < 4; j++) {
            int ci = j * 256 + t;
            int va = (bm + ar[j]) < M ? 16 : 0;
            size_t ao = (size_t)(bm + ar[j]) * K + (ci & 7) * 8;
            cpa16(s0 + adsw[j],         Ahi + ao, va);
            cpa16(s0 + 16384 + adsw[j], Alo + ao, va);
        }
        #pragma unroll
        for (int j = 0; j < 2; j++) {
            int ci = j * 256 + t;
            size_t bo = (size_t)(bn + bw_r[j]) * K + (ci & 7) * 8;
            cpa16(s0 + 32768 + bdsw[j], Bhi + bo, 16);
            cpa16(s0 + 40960 + bdsw[j], Blo + bo, 16);
        }
        CP_COMMIT();
    }

    for (int ki = 0; ki < nk; ki++) {
        if (ki + 1 < nk) {
            uint32_t sn = sb + ((ki + 1) & 1) * GSTAGE;
            int kc = (ki + 1) * BK;
            #pragma unroll
            for (int j = 0; j < 4; j++) {
                int ci = j * 256 + t;
                int va = (bm + ar[j]) < M ? 16 : 0;
                size_t ao = (size_t)(bm + ar[j]) * K + kc + (ci & 7) * 8;
                cpa16(sn + adsw[j],         Ahi + ao, va);
                cpa16(sn + 16384 + adsw[j], Alo + ao, va);
            }
            #pragma unroll
            for (int j = 0; j < 2; j++) {
                int ci = j * 256 + t;
                size_t bo = (size_t)(bn + bw_r[j]) * K + kc + (ci & 7) * 8;
                cpa16(sn + 32768 + bdsw[j], Bhi + bo, 16);
                cpa16(sn + 40960 + bdsw[j], Blo + bo, 16);
            }
        }
        CP_COMMIT();
        CP_WAIT1();
        __syncthreads();

        uint32_t sAh = sb + (ki & 1) * GSTAGE;
        uint32_t sAl = sAh + 16384, sBh = sAh + 32768, sBl = sAh + 40960;

        #pragma unroll
        for (int ks = 0; ks < 4; ks++) {
            uint32_t bh[8], bl[8], a4[2][4];
            #pragma unroll
            for (int j = 0; j < 2; j++) {
                ldm4(&bh[j * 4], swaddr(sBh, nbw + j * 16, ks, lane));
                ldm4(&bl[j * 4], swaddr(sBl, nbw + j * 16, ks, lane));
            }
            #pragma unroll
            for (int mi = 0; mi < 2; mi++)
                ldm4(a4[mi], swaddr(sAh, rmw + mi * 16, ks, lane));
            #pragma unroll
            for (int mi = 0; mi < 2; mi++)
                #pragma unroll
                for (int j2 = 0; j2 < 4; j2++) {
                    int base = (j2 >> 1) * 4, sel = j2 & 1;
                    mma16816(acc[mi][j2], a4[mi], bh[base + sel], bh[base + 2 + sel]);
                    mma16816(acc[mi][j2], a4[mi], bl[base + sel], bl[base + 2 + sel]);
                }
            #pragma unroll
            for (int mi = 0; mi < 2; mi++)
                ldm4(a4[mi], swaddr(sAl, rmw + mi * 16, ks, lane));
            #pragma unroll
            for (int mi = 0; mi < 2; mi++)
                #pragma unroll
                for (int j2 = 0; j2 < 4; j2++) {
                    int base = (j2 >> 1) * 4, sel = j2 & 1;
                    mma16816(acc[mi][j2], a4[mi], bh[base + sel], bh[base + 2 + sel]);
                }
        }
        __syncthreads();
    }

    // ---- epilogue ----
    int r0 = lane >> 2, c0 = (lane & 3) * 2;
    #pragma unroll
    for (int mi = 0; mi < 2; mi++) {
        #pragma unroll
        for (int j2 = 0; j2 < 4; j2++) {
            int gn = bn + nbw + j2 * 8 + c0;
            float b0 = 0.f, b1 = 0.f;
            if (bias) { b0 = bias[gn]; b1 = bias[gn + 1]; }
            float l0 = 0.f, l1 = 0.f;
            if (mode == 2) { l0 = lam[gn]; l1 = lam[gn + 1]; }
            #pragma unroll
            for (int half = 0; half < 2; half++) {
                int gm = bm + rmw + mi * 16 + r0 + half * 8;
                if (gm >= M) continue;
                float vx = acc[mi][j2][half * 2 + 0] + b0;
                float vy = acc[mi][j2][half * 2 + 1] + b1;
                if (mode == 1) {
                    vx = 0.5f * vx * (1.0f + erff(vx * 0.70710678118654752f));
                    vy = 0.5f * vy * (1.0f + erff(vy * 0.70710678118654752f));
                    uint32_t hi, lo;
                    split2(vx, vy, hi, lo);
                    size_t o = (size_t)gm * N + gn;
                    *(uint32_t*)(Chi + o) = hi;
                    *(uint32_t*)(Clo + o) = lo;
                } else {
                    if (mode == 2) {
                        const float2 rv = *(const float2*)(res + (size_t)gm * N + gn);
                        vx = rv.x + vx * l0;
                        vy = rv.y + vy * l1;
                    }
                    *(float2*)(C + (size_t)gm * N + gn) = make_float2(vx, vy);
                }
            }
        }
    }
}

// ---------------------------------------------------------------------------
// Patch embed
// ---------------------------------------------------------------------------
__global__ void embed_kernel(const float* __restrict__ x, const float* __restrict__ cls,
                             float* __restrict__ h)
{
    int i = blockIdx.x * 256 + threadIdx.x;
    if (i >= MROWS * DM) return;
    int c = i % DM;
    int s = (i / DM) % SEQ;
    int b = i / (DM * SEQ);
    h[i] = (s == 0) ? cls[c] : x[((size_t)(b * 196 + s - 1)) * DM + c];
}

// ---------------------------------------------------------------------------
// LayerNorm -> bf16 hi/lo planes
// ---------------------------------------------------------------------------
__global__ void ln_kernel(const float* __restrict__ x, const float* __restrict__ g,
                          const float* __restrict__ bta,
                          bf16* __restrict__ yhi, bf16* __restrict__ ylo)
{
    int row = blockIdx.x;
    const float* xr = x + (size_t)row * DM;
    int t = threadIdx.x;
    float v0 = xr[t], v1 = xr[t + 256], v2 = xr[t + 512];
    __shared__ float sh[8];

    float s = v0 + v1 + v2;
    #pragma unroll
    for (int o = 16; o; o >>= 1) s += __shfl_xor_sync(0xffffffffu, s, o);
    if ((t & 31) == 0) sh[t >> 5] = s;
    __syncthreads();
    if (t == 0) { float tot = 0.f; for (int i = 0; i < 8; i++) tot += sh[i]; sh[0] = tot; }
    __syncthreads();
    float mean = sh[0] * (1.0f / 768.0f);
    __syncthreads();

    float d0 = v0 - mean, d1 = v1 - mean, d2 = v2 - mean;
    s = d0 * d0 + d1 * d1 + d2 * d2;
    #pragma unroll
    for (int o = 16; o; o >>= 1) s += __shfl_xor_sync(0xffffffffu, s, o);
    if ((t & 31) == 0) sh[t >> 5] = s;
    __syncthreads();
    if (t == 0) { float tot = 0.f; for (int i = 0; i < 8; i++) tot += sh[i]; sh[0] = tot; }
    __syncthreads();
    float rstd = rsqrtf(sh[0] * (1.0f / 768.0f) + 1e-12f);

    size_t base = (size_t)row * DM;
    #pragma unroll
    for (int j = 0; j < 3; j++) {
        int col = t + j * 256;
        float d = (j == 0) ? d0 : (j == 1) ? d1 : d2;
        float v = d * rstd * g[col] + bta[col];
        bf16 h = __float2bfloat16_rn(v);
        yhi[base + col] = h;
        ylo[base + col] = __float2bfloat16_rn(v - __bfloat162float(h));
    }
}

// ---------------------------------------------------------------------------
// Attention: qkv fused input [M][2304], rel column preloaded to smem.
// ---------------------------------------------------------------------------
__device__ __forceinline__ int relidx(int q, int k)
{
    if (q == 0 && k == 0) return NDREL - 1;
    if (q == 0)           return NDREL - 3;
    if (k == 0)           return NDREL - 2;
    int p = q - 1, r = k - 1;
    int di = p / 14 - r / 14 + 13;
    int dj = p % 14 - r % 14 + 13;
    return di * 27 + dj;
}

#define KS_PITCH 65
#define ATT_SMEM_FLOATS (2 * SEQ * KS_PITCH + 8 * 64 + 8 * 200 + NDREL)
#define ATT_SMEM_BYTES  (ATT_SMEM_FLOATS * 4)

__global__ void attn_kernel(const float* __restrict__ qkv, const float* __restrict__ rel,
                            bf16* __restrict__ chi, bf16* __restrict__ clo)
{
    int h = blockIdx.x, b = blockIdx.y;
    extern __shared__ float sm[];
    float* Ks   = sm;
    float* Vs   = sm + SEQ * KS_PITCH;
    float* qs   = sm + 2 * SEQ * KS_PITCH;
    float* Ps   = qs + 8 * 64;
    float* rels = Ps + 8 * 200;

    int t = threadIdx.x;
    for (int idx = t; idx < SEQ * HD; idx += 256) {
        int kk = idx >> 6, d = idx & 63;
        size_t g = (size_t)(b * SEQ + kk) * NQKV + h * HD + d;
        Ks[kk * KS_PITCH + d] = qkv[g + DM];
        Vs[kk * KS_PITCH + d] = qkv[g + 2 * DM];
    }
    for (int idx = t; idx < NDREL; idx += 256)
        rels[idx] = rel[idx * NH + h];
    __syncthreads();

    int w = t >> 5, lane = t & 31;
    for (int q = w; q < SEQ; q += 8) {
        size_t qbase = (size_t)(b * SEQ + q) * NQKV + h * HD;
        qs[w * 64 + lane]      = qkv[qbase + lane];
        qs[w * 64 + lane + 32] = qkv[qbase + lane + 32];
        __syncwarp();

        float s[7];
        float mx = -1e30f;
        #pragma unroll
        for (int j = 0; j < 7; j++) {
            int kk = lane + j * 32;
            float acc = -1e30f;
            if (kk < SEQ) {
                float v = 0.f;
                #pragma unroll
                for (int d = 0; d < HD; d++) v += qs[w * 64 + d] * Ks[kk * KS_PITCH + d];
                acc = v * 0.125f + rels[relidx(q, kk)];
            }
            s[j] = acc;
            mx = fmaxf(mx, acc);
        }
        #pragma unroll
        for (int o = 16; o; o >>= 1) mx = fmaxf(mx, __shfl_xor_sync(0xffffffffu, mx, o));

        float sum = 0.f;
        #pragma unroll
        for (int j = 0; j < 7; j++) {
            int kk = lane + j * 32;
            float e = (kk < SEQ) ? expf(s[j] - mx) : 0.f;
            s[j] = e;
            sum += e;
        }
        #pragma unroll
        for (int o = 16; o; o >>= 1) sum += __shfl_xor_sync(0xffffffffu, sum, o);
        float inv = 1.0f / sum;

        #pragma unroll
        for (int j = 0; j < 7; j++) {
            int kk = lane + j * 32;
            if (kk < SEQ) Ps[w * 200 + kk] = s[j] * inv;
        }
        __syncwarp();

        float a0 = 0.f, a1 = 0.f;
        for (int kk = 0; kk < SEQ; kk++) {
            float p = Ps[w * 200 + kk];
            a0 += p * Vs[kk * KS_PITCH + lane];
            a1 += p * Vs[kk * KS_PITCH + lane + 32];
        }
        size_t cbase = (size_t)(b * SEQ + q) * DM + h * HD;
        bf16 h0 = __float2bfloat16_rn(a0);
        bf16 h1 = __float2bfloat16_rn(a1);
        chi[cbase + lane]      = h0;
        chi[cbase + lane + 32] = h1;
        clo[cbase + lane]      = __float2bfloat16_rn(a0 - __bfloat162float(h0));
        clo[cbase + lane + 32] = __float2bfloat16_rn(a1 - __bfloat162float(h1));
        __syncwarp();
    }
}

// ---------------------------------------------------------------------------
// Orchestration
// ---------------------------------------------------------------------------
extern "C" void kernel_launch(void* const* d_in, const int* in_sizes, int n_in,
                              void* d_out, int out_size)
{
    const float* x    = (const float*)d_in[0];
    const float* cls  = (const float*)d_in[1];
    const float* g1   = (const float*)d_in[2];
    const float* b1   = (const float*)d_in[3];
    const float* Wq   = (const float*)d_in[4];
    const float* bq   = (const float*)d_in[5];
    const float* Wk   = (const float*)d_in[6];
    const float* Wv   = (const float*)d_in[7];
    const float* bv   = (const float*)d_in[8];
    const float* rel  = (const float*)d_in[9];
    const float* Wo   = (const float*)d_in[10];
    const float* bo   = (const float*)d_in[11];
    const float* lam1 = (const float*)d_in[12];
    const float* g2   = (const float*)d_in[13];
    const float* b2   = (const float*)d_in[14];
    const float* Wi   = (const float*)d_in[15];
    const float* bi   = (const float*)d_in[16];
    const float* Wmo  = (const float*)d_in[17];
    const float* bmo  = (const float*)d_in[18];
    const float* lam2 = (const float*)d_in[19];

    float *h, *qkv, *bqkv;
    bf16 *hnh, *hnl, *cth, *ctl, *fh, *fl;
    bf16 *wqh, *wql, *woh, *wol, *wih, *wil, *wmh, *wml;
    cudaGetSymbolAddress((void**)&h,    g_h);
    cudaGetSymbolAddress((void**)&qkv,  g_qkv);
    cudaGetSymbolAddress((void**)&bqkv, g_bqkv);
    cudaGetSymbolAddress((void**)&hnh,  g_hn_hi);
    cudaGetSymbolAddress((void**)&hnl,  g_hn_lo);
    cudaGetSymbolAddress((void**)&cth,  g_ctx_hi);
    cudaGetSymbolAddress((void**)&ctl,  g_ctx_lo);
    cudaGetSymbolAddress((void**)&fh,   g_f_hi);
    cudaGetSymbolAddress((void**)&fl,   g_f_lo);
    cudaGetSymbolAddress((void**)&wqh,  g_wqkv_hi);
    cudaGetSymbolAddress((void**)&wql,  g_wqkv_lo);
    cudaGetSymbolAddress((void**)&woh,  g_wo_hi);
    cudaGetSymbolAddress((void**)&wol,  g_wo_lo);
    cudaGetSymbolAddress((void**)&wih,  g_wi_hi);
    cudaGetSymbolAddress((void**)&wil,  g_wi_lo);
    cudaGetSymbolAddress((void**)&wmh,  g_wmo_hi);
    cudaGetSymbolAddress((void**)&wml,  g_wmo_lo);

    cudaFuncSetAttribute(attn_kernel, cudaFuncAttributeMaxDynamicSharedMemorySize,
                         ATT_SMEM_BYTES);
    cudaFuncSetAttribute(mmagemm, cudaFuncAttributeMaxDynamicSharedMemorySize,
                         GEMM_SMEM);

    // weight conversion (transpose + hi/lo split)
    dim3 cb(32, 8);
    for (int l = 0; l < 3; l++) {
        size_t wo  = (size_t)l * DM * DM;
        size_t wio = (size_t)l * DM * DF;
        bf16* qh = wqh + (size_t)l * NQKV * DM;
        bf16* ql = wql + (size_t)l * NQKV * DM;
        convw<<<dim3(DM / 32, DM / 32), cb>>>(Wq + wo, qh,                ql,                DM, DM);
        convw<<<dim3(DM / 32, DM / 32), cb>>>(Wk + wo, qh + DM * DM,      ql + DM * DM,      DM, DM);
        convw<<<dim3(DM / 32, DM / 32), cb>>>(Wv + wo, qh + 2 * DM * DM,  ql + 2 * DM * DM,  DM, DM);
        convw<<<dim3(DM / 32, DM / 32), cb>>>(Wo + wo, woh + wo, wol + wo, DM, DM);
        convw<<<dim3(DF / 32, DM / 32), cb>>>(Wi + wio, wih + (size_t)l * DF * DM,
                                              wil + (size_t)l * DF * DM, DM, DF);
        convw<<<dim3(DM / 32, DF / 32), cb>>>(Wmo + wio, wmh + (size_t)l * DM * DF,
                                              wml + (size_t)l * DM * DF, DF, DM);
    }
    mkbias<<<(NQKV + 255) / 256, 256>>>(bq, bv, bqkv);   // layer-indep? no: bq per layer

    embed_kernel<<<(MROWS * DM + 255) / 256, 256>>>(x, cls, h);

    int mt = (MROWS + TM - 1) / TM;        // 99
    dim3 gqkv(NQKV / TN, mt);              // (36, 99)
    dim3 g768(DM / TN, mt);                // (12, 99)
    dim3 g3072(DF / TN, mt);               // (48, 99)

    for (int l = 0; l < 3; l++) {
        bf16* qh  = wqh + (size_t)l * NQKV * DM;
        bf16* ql  = wql + (size_t)l * NQKV * DM;
        bf16* oh  = woh + (size_t)l * DM * DM;
        bf16* ol  = wol + (size_t)l * DM * DM;
        bf16* ih  = wih + (size_t)l * DF * DM;
        bf16* il  = wil + (size_t)l * DF * DM;
        bf16* mh  = wmh + (size_t)l * DM * DF;
        bf16* ml  = wml + (size_t)l * DM * DF;

        mkbias<<<(NQKV + 255) / 256, 256>>>(bq + l * DM, bv + l * DM, bqkv);

        ln_kernel<<<MROWS, 256>>>(h, g1 + l * DM, b1 + l * DM, hnh, hnl);

        mmagemm<<<gqkv, 256, GEMM_SMEM>>>(hnh, hnl, qh, ql, bqkv,
                                          nullptr, nullptr, qkv, nullptr, nullptr,
                                          MROWS, NQKV, DM, 0);

        attn_kernel<<<dim3(NH, NB), 256, ATT_SMEM_BYTES>>>(
            qkv, rel + (size_t)l * NDREL * NH, cth, ctl);

        mmagemm<<<g768, 256, GEMM_SMEM>>>(cth, ctl, oh, ol, bo + l * DM,
                                          h, lam1 + l * DM, h, nullptr, nullptr,
                                          MROWS, DM, DM, 2);

        ln_kernel<<<MROWS, 256>>>(h, g2 + l * DM, b2 + l * DM, hnh, hnl);

        mmagemm<<<g3072, 256, GEMM_SMEM>>>(hnh, hnl, ih, il, bi + l * DF,
                                           nullptr, nullptr, nullptr, fh, fl,
                                           MROWS, DF, DM, 1);

        mmagemm<<<g768, 256, GEMM_SMEM>>>(fh, fl, mh, ml, bmo + l * DM,
                                          h, lam2 + l * DM,
                                          (l == 2) ? (float*)d_out : h, nullptr, nullptr,
                                          MROWS, DM, DF, 2);
    }
}